// round 16
// baseline (speedup 1.0000x reference)
#include <cuda_runtime.h>
#include <math.h>
#include <stdint.h>

#define N_AG 65536
#define G_NUM 1024

static __device__ float g_inter_emb[(size_t)N_AG * 64];
static __device__ float g_intra_emb[(size_t)N_AG * 64];
static __device__ float g_pooled[G_NUM * 64];
static __device__ float g_qkv_inter[G_NUM * 384];
static __device__ float g_att_inter[G_NUM * 128];

__device__ __forceinline__ uint32_t f2tf32(float x) {
    uint32_t u;
    asm("cvt.rna.tf32.f32 %0, %1;" : "=r"(u) : "f"(x));
    return u;
}

__device__ __forceinline__ void mma_tf32(float* c, const uint32_t* a, const uint32_t* b) {
    asm volatile("mma.sync.aligned.m16n8k8.row.col.f32.tf32.tf32.f32 "
        "{%0,%1,%2,%3}, {%4,%5,%6,%7}, {%8,%9}, {%0,%1,%2,%3};"
        : "+f"(c[0]), "+f"(c[1]), "+f"(c[2]), "+f"(c[3])
        : "r"(a[0]), "r"(a[1]), "r"(a[2]), "r"(a[3]), "r"(b[0]), "r"(b[1]));
}

__device__ __forceinline__ void cp_async16(uint32_t smem_addr, const void* gptr) {
    asm volatile("cp.async.ca.shared.global [%0], [%1], 16;" :: "r"(smem_addr), "l"(gptr));
}
__device__ __forceinline__ void cp_commit() {
    asm volatile("cp.async.commit_group;");
}
template <int N>
__device__ __forceinline__ void cp_wait() {
    asm volatile("cp.async.wait_group %0;" :: "n"(N));
}

__device__ __forceinline__ float ftanh(float x) {
    // 1 - 2/(e^{2x}+1); saturates correctly for |x| large.
    return 1.f - __fdividef(2.f, __expf(2.f * x) + 1.f);
}

// ====== Kernel A: embedding GEMM (TF32 MMA, 3-stage cp.async ring, 1 sync/chunk) ======
#define EMB_STAGE 9216
#define EMB_NSTAGE 3
__global__ void __launch_bounds__(256) k_emb_tc(const float* __restrict__ obs,
    const float* __restrict__ lw, const float* __restrict__ lb,
    const float* __restrict__ iew, const float* __restrict__ ieb,
    const float* __restrict__ aew, const float* __restrict__ aeb,
    float* __restrict__ out)
{
    extern __shared__ uint32_t dynsm[];
    const int tid = threadIdx.x;
    const int lane = tid & 31, warp = tid >> 5;
    const int wm = warp >> 2, wn = warp & 3;
    const int gid = lane >> 2, tg = lane & 3;
    const int m0 = blockIdx.x * 128, j0 = blockIdx.y * 128;

    const float* agp[4];
    const float* wgp[4];
    uint32_t sa_off[4], sw_off[4];
#pragma unroll
    for (int l = 0; l < 4; l++) {
        int slot = tid + l * 256;
        int r = slot >> 3, kq = slot & 7;
        agp[l] = obs + (size_t)(m0 + r) * 256 + kq * 4;
        int j = j0 + r;
        const float* wr = (j < 512) ? (lw + (size_t)j * 256)
                        : (j < 576) ? (iew + (size_t)(j - 512) * 256)
                        : (aew + (size_t)(j - 576) * 256);
        wgp[l] = wr + kq * 4;
        uint32_t base = (uint32_t)__cvta_generic_to_shared(dynsm);
        sa_off[l] = base + (r * 36 + kq * 4) * 4;
        sw_off[l] = base + (4608 + r * 36 + kq * 4) * 4;
    }

    float acc[4][4][4];
#pragma unroll
    for (int i = 0; i < 4; i++)
#pragma unroll
        for (int j = 0; j < 4; j++)
#pragma unroll
            for (int u = 0; u < 4; u++) acc[i][j][u] = 0.f;

    // prologue: prefetch chunks 0 and 1 into stages 0 and 1
#pragma unroll
    for (int s = 0; s < 2; s++) {
        uint32_t soff = s * (EMB_STAGE * 4);
#pragma unroll
        for (int l = 0; l < 4; l++) {
            cp_async16(sa_off[l] + soff, agp[l] + s * 32);
            cp_async16(sw_off[l] + soff, wgp[l] + s * 32);
        }
        cp_commit();
    }

    int stage = 0;
    for (int kc = 0; kc < 8; kc++) {
        if (kc + 1 < 8) { cp_wait<1>(); } else { cp_wait<0>(); }
        __syncthreads();
        if (kc + 2 < 8) {
            int ns = stage + 2; if (ns >= EMB_NSTAGE) ns -= EMB_NSTAGE;
            uint32_t soff = ns * (EMB_STAGE * 4);
#pragma unroll
            for (int l = 0; l < 4; l++) {
                cp_async16(sa_off[l] + soff, agp[l] + (kc + 2) * 32);
                cp_async16(sw_off[l] + soff, wgp[l] + (kc + 2) * 32);
            }
            cp_commit();
        }
        const uint32_t* As = dynsm + stage * EMB_STAGE;
        const uint32_t* Ws = As + 4608;
#pragma unroll
        for (int k8 = 0; k8 < 4; k8++) {
            int kb = k8 * 8;
            uint32_t a[4][4], b[4][2];
#pragma unroll
            for (int mt = 0; mt < 4; mt++) {
                int row = wm * 64 + mt * 16;
                a[mt][0] = As[(row + gid) * 36 + kb + tg];
                a[mt][1] = As[(row + gid + 8) * 36 + kb + tg];
                a[mt][2] = As[(row + gid) * 36 + kb + tg + 4];
                a[mt][3] = As[(row + gid + 8) * 36 + kb + tg + 4];
            }
#pragma unroll
            for (int nt = 0; nt < 4; nt++) {
                int col = wn * 32 + nt * 8;
                b[nt][0] = Ws[(col + gid) * 36 + kb + tg];
                b[nt][1] = Ws[(col + gid) * 36 + kb + tg + 4];
            }
#pragma unroll
            for (int mt = 0; mt < 4; mt++)
#pragma unroll
                for (int nt = 0; nt < 4; nt++)
                    mma_tf32(acc[mt][nt], a[mt], b[nt]);
        }
        stage++; if (stage >= EMB_NSTAGE) stage = 0;
    }

#pragma unroll
    for (int mt = 0; mt < 4; mt++) {
#pragma unroll
        for (int nt = 0; nt < 4; nt++) {
            int col = j0 + wn * 32 + nt * 8 + 2 * tg;
#pragma unroll
            for (int half = 0; half < 2; half++) {
                int row = m0 + wm * 64 + mt * 16 + gid + half * 8;
                float v0 = acc[mt][nt][half * 2 + 0];
                float v1 = acc[mt][nt][half * 2 + 1];
                float2 r2;
                if (col < 512) {
                    r2.x = ftanh(v0 + lb[col]); r2.y = ftanh(v1 + lb[col + 1]);
                    *(float2*)(out + (size_t)row * 640 + col) = r2;
                } else if (col < 576) {
                    int c = col - 512;
                    r2.x = ftanh(v0 + ieb[c]); r2.y = ftanh(v1 + ieb[c + 1]);
                    *(float2*)(g_inter_emb + (size_t)row * 64 + c) = r2;
                } else {
                    int c = col - 576;
                    r2.x = ftanh(v0 + aeb[c]); r2.y = ftanh(v1 + aeb[c + 1]);
                    *(float2*)(g_intra_emb + (size_t)row * 64 + c) = r2;
                }
            }
        }
    }
}

// ======== Kernel B: fused intra path, 512 threads (QKV + attention + out-proj + pool) ========
#define OFF_IE  4352
#define OFF_QKV 8704
#define OFF_ATT 33792
#define OFF_W   42496
#define OFF_LG  55552
#define OFF_PR  55616
#define SMEM_FUSED_FLOATS 55680

__global__ void __launch_bounds__(512) k_intra_fused(const int* __restrict__ sets,
    const float* __restrict__ wmu_in, const float* __restrict__ bmu_in,
    const float* __restrict__ wsd_in, const float* __restrict__ bsd_in,
    const float* __restrict__ wmu_out, const float* __restrict__ bmu_out,
    const float* __restrict__ wsd_out, const float* __restrict__ bsd_out,
    const float* __restrict__ aw, const float* __restrict__ ab,
    const float* __restrict__ eps, float* __restrict__ out)
{
    extern __shared__ float sm[];
    float* s_emb = sm;
    float* s_ie  = sm + OFF_IE;
    float* s_qkv = sm + OFF_QKV;
    float* s_att = sm + OFF_ATT;
    float* s_w   = sm + OFF_W;
    float* s_lg  = sm + OFF_LG;
    float* s_pr  = sm + OFF_PR;

    const int g = blockIdx.x, tid = threadIdx.x;
    const int lane = tid & 31, warp = tid >> 5;
    const int gid = lane >> 2, tg = lane & 3;

#pragma unroll
    for (int l = 0; l < 2; l++) {
        int idx = tid + l * 512;
        int r = idx >> 4, c4 = (idx & 15) * 4;
        int agent = sets[g * 64 + r];
        *(float4*)(s_emb + r * 68 + c4) = *(const float4*)(g_intra_emb + (size_t)agent * 64 + c4);
        *(float4*)(s_ie + r * 68 + c4)  = *(const float4*)(g_inter_emb + (size_t)agent * 64 + c4);
    }
    __syncthreads();

    if (tid < 64) {
        float a = ab[0];
#pragma unroll 8
        for (int d = 0; d < 64; d++) a += s_ie[tid * 68 + d] * aw[d];
        s_lg[tid] = a;
    }
#pragma unroll
    for (int l = 0; l < 6; l++) {
        int idx = tid + l * 512;
        int r = idx >> 4, c4 = (idx & 15) * 4;
        *(float4*)(s_w + r * 68 + c4) = *(const float4*)(wmu_in + (size_t)r * 64 + c4);
    }
    __syncthreads();

    if (tid < 64) {
        float mx = -1e30f;
        for (int s = 0; s < 64; s++) mx = fmaxf(mx, s_lg[s]);
        s_pr[tid] = __expf(s_lg[tid] - mx);
    }
    {
        const int wm = warp >> 2, wn = warp & 3;
        float acc[6][4];
#pragma unroll
        for (int nt = 0; nt < 6; nt++)
#pragma unroll
            for (int u = 0; u < 4; u++) acc[nt][u] = 0.f;
#pragma unroll
        for (int k8 = 0; k8 < 8; k8++) {
            int kb = k8 * 8;
            uint32_t a[4];
            a[0] = f2tf32(s_emb[(wm*16+gid)*68 + kb+tg]);
            a[1] = f2tf32(s_emb[(wm*16+gid+8)*68 + kb+tg]);
            a[2] = f2tf32(s_emb[(wm*16+gid)*68 + kb+tg+4]);
            a[3] = f2tf32(s_emb[(wm*16+gid+8)*68 + kb+tg+4]);
#pragma unroll
            for (int nt = 0; nt < 6; nt++) {
                int col = wn * 48 + nt * 8;
                uint32_t b[2];
                b[0] = f2tf32(s_w[(col+gid)*68 + kb+tg]);
                b[1] = f2tf32(s_w[(col+gid)*68 + kb+tg+4]);
                mma_tf32(acc[nt], a, b);
            }
        }
#pragma unroll
        for (int nt = 0; nt < 6; nt++) {
            int col = wn * 48 + nt * 8 + 2 * tg;
            float b0 = bmu_in[col], b1 = bmu_in[col + 1];
            *(float2*)(s_qkv + (wm*16+gid)*196 + col)   = make_float2(acc[nt][0]+b0, acc[nt][1]+b1);
            *(float2*)(s_qkv + (wm*16+gid+8)*196 + col) = make_float2(acc[nt][2]+b0, acc[nt][3]+b1);
        }
    }
    __syncthreads();

    if (tid < 64) {
        float sum = 0.f, acc = 0.f;
        for (int s = 0; s < 64; s++) sum += s_pr[s];
        for (int s = 0; s < 64; s++) acc += s_pr[s] * s_ie[s * 68 + tid];
        g_pooled[g * 64 + tid] = acc / sum;
    }
#pragma unroll
    for (int l = 0; l < 6; l++) {
        int idx = tid + l * 512;
        int r = idx >> 4, c4 = (idx & 15) * 4;
        *(float4*)(s_w + r * 68 + c4) = *(const float4*)(wsd_in + (size_t)r * 64 + c4);
    }
    __syncthreads();

    {
        const int wm = warp >> 2, wn = warp & 3;
        float acc[6][4];
#pragma unroll
        for (int nt = 0; nt < 6; nt++)
#pragma unroll
            for (int u = 0; u < 4; u++) acc[nt][u] = 0.f;
#pragma unroll
        for (int k8 = 0; k8 < 8; k8++) {
            int kb = k8 * 8;
            uint32_t a[4];
            a[0] = f2tf32(s_emb[(wm*16+gid)*68 + kb+tg]);
            a[1] = f2tf32(s_emb[(wm*16+gid+8)*68 + kb+tg]);
            a[2] = f2tf32(s_emb[(wm*16+gid)*68 + kb+tg+4]);
            a[3] = f2tf32(s_emb[(wm*16+gid+8)*68 + kb+tg+4]);
#pragma unroll
            for (int nt = 0; nt < 6; nt++) {
                int col = wn * 48 + nt * 8;
                uint32_t b[2];
                b[0] = f2tf32(s_w[(col+gid)*68 + kb+tg]);
                b[1] = f2tf32(s_w[(col+gid)*68 + kb+tg+4]);
                mma_tf32(acc[nt], a, b);
            }
        }
#pragma unroll
        for (int nt = 0; nt < 6; nt++) {
            int col = wn * 48 + nt * 8 + 2 * tg;
            float b0 = bsd_in[col], b1 = bsd_in[col + 1];
            *(float2*)(s_qkv + 12544 + (wm*16+gid)*196 + col)   = make_float2(acc[nt][0]+b0, acc[nt][1]+b1);
            *(float2*)(s_qkv + 12544 + (wm*16+gid+8)*196 + col) = make_float2(acc[nt][2]+b0, acc[nt][3]+b1);
        }
    }
    __syncthreads();

#pragma unroll
    for (int l = 0; l < 4; l++) {
        int idx = tid + l * 512;
        int w = idx >> 10, r = (idx >> 4) & 63, c4 = (idx & 15) * 4;
        *(float4*)(s_w + w * 4352 + r * 68 + c4) =
            *(const float4*)((w ? wsd_out : wmu_out) + (size_t)r * 64 + c4);
    }
    {
        const int w = tid >> 8, h = (tid >> 6) & 3, i = tid & 63;
        const float* base = s_qkv + w * 12544;
        float4 qv[4];
        const float4* qp = (const float4*)(base + i * 196 + h * 16);
#pragma unroll
        for (int u = 0; u < 4; u++) {
            qv[u] = qp[u];
            qv[u].x *= 0.25f; qv[u].y *= 0.25f; qv[u].z *= 0.25f; qv[u].w *= 0.25f;
        }
        float sum = 0.f;
        float4 o[4];
#pragma unroll
        for (int u = 0; u < 4; u++) o[u] = make_float4(0.f, 0.f, 0.f, 0.f);
        for (int j = 0; j < 64; j++) {
            const float4* kr = (const float4*)(base + j * 196 + 64 + h * 16);
            float s = 0.f;
#pragma unroll
            for (int u = 0; u < 4; u++) {
                float4 k = kr[u];
                s += qv[u].x * k.x + qv[u].y * k.y + qv[u].z * k.z + qv[u].w * k.w;
            }
            float p = __expf(s);
            sum += p;
            const float4* vr = (const float4*)(base + j * 196 + 128 + h * 16);
#pragma unroll
            for (int u = 0; u < 4; u++) {
                float4 v = vr[u];
                o[u].x += p * v.x; o[u].y += p * v.y; o[u].z += p * v.z; o[u].w += p * v.w;
            }
        }
        float inv = 1.f / sum;
        float4* op = (float4*)(s_att + w * 4352 + i * 68 + h * 16);
#pragma unroll
        for (int u = 0; u < 4; u++)
            op[u] = make_float4(o[u].x * inv, o[u].y * inv, o[u].z * inv, o[u].w * inv);
    }
    __syncthreads();

    {
        const int w = warp >> 3, ww = warp & 7;
        const int wm2 = ww >> 1, wn2 = ww & 1;
        const float* A = s_att + w * 4352;
        const float* B = s_w + w * 4352;
        const float* bb = w ? bsd_out : bmu_out;
        float am[4][4];
#pragma unroll
        for (int nt = 0; nt < 4; nt++)
#pragma unroll
            for (int u = 0; u < 4; u++) am[nt][u] = 0.f;
#pragma unroll
        for (int k8 = 0; k8 < 8; k8++) {
            int kb = k8 * 8;
            uint32_t a[4];
            a[0] = f2tf32(A[(wm2*16+gid)*68 + kb+tg]);
            a[1] = f2tf32(A[(wm2*16+gid+8)*68 + kb+tg]);
            a[2] = f2tf32(A[(wm2*16+gid)*68 + kb+tg+4]);
            a[3] = f2tf32(A[(wm2*16+gid+8)*68 + kb+tg+4]);
#pragma unroll
            for (int nt = 0; nt < 4; nt++) {
                int col = wn2 * 32 + nt * 8;
                uint32_t b[2];
                b[0] = f2tf32(B[(col+gid)*68 + kb+tg]);
                b[1] = f2tf32(B[(col+gid)*68 + kb+tg+4]);
                mma_tf32(am[nt], a, b);
            }
        }
#pragma unroll
        for (int nt = 0; nt < 4; nt++) {
            int col = wn2 * 32 + nt * 8 + 2 * tg;
            float b0 = bb[col], b1 = bb[col + 1];
#pragma unroll
            for (int half = 0; half < 2; half++) {
                int row = wm2 * 16 + gid + half * 8;
                *(float2*)(s_qkv + w * 4352 + row * 68 + col) =
                    make_float2(am[nt][half*2+0] + b0, am[nt][half*2+1] + b1);
            }
        }
    }
    __syncthreads();

    {
        const int i = tid >> 3, c0 = (tid & 7) * 8;
        const int agent = sets[g * 64 + i];
        const size_t MU0 = (size_t)N_AG * 640, SD0 = MU0 + (size_t)N_AG * 128;
        float mu[8], sd[8], sa[8];
#pragma unroll
        for (int jj = 0; jj < 8; jj++) {
            mu[jj] = s_qkv[i * 68 + c0 + jj];
            float z = s_qkv[4352 + i * 68 + c0 + jj] - 5.f;
            sd[jj] = (z > 20.f) ? z : log1pf(__expf(z));
        }
#pragma unroll
        for (int jj = 0; jj < 8; jj++)
            sa[jj] = mu[jj] + sd[jj] * eps[(size_t)agent * 64 + c0 + jj];
        float* oa = out + (size_t)agent * 640 + 576 + c0;
        float* om = out + MU0 + (size_t)agent * 128 + c0;
        float* os = out + SD0 + (size_t)agent * 128 + c0;
#pragma unroll
        for (int jj = 0; jj < 8; jj += 4) {
            *(float4*)(oa + jj) = make_float4(sa[jj], sa[jj+1], sa[jj+2], sa[jj+3]);
            *(float4*)(om + jj) = make_float4(mu[jj], mu[jj+1], mu[jj+2], mu[jj+3]);
            *(float4*)(os + jj) = make_float4(sd[jj], sd[jj+1], sd[jj+2], sd[jj+3]);
        }
    }
}

// ---- Kernel F: inter QKV GEMM (small, fp32) ----
__global__ void __launch_bounds__(256) k_qkv_inter_k(
    const float* __restrict__ wmu, const float* __restrict__ bmu,
    const float* __restrict__ wsd, const float* __restrict__ bsd)
{
    __shared__ float As[16][132];
    __shared__ float Ws[16][132];
    const int tid = threadIdx.x, tx = tid & 15, ty = tid >> 4;
    const int m0 = blockIdx.x * 128, j0 = blockIdx.y * 128;
    float acc[8][8];
#pragma unroll
    for (int i = 0; i < 8; i++)
#pragma unroll
        for (int j = 0; j < 8; j++) acc[i][j] = 0.f;
    for (int k0 = 0; k0 < 64; k0 += 16) {
#pragma unroll
        for (int l = 0; l < 2; l++) {
            int idx = tid + l * 256;
            int r = idx >> 2, kq = idx & 3;
            float4 va = *(const float4*)(g_pooled + (size_t)(m0 + r) * 64 + k0 + kq * 4);
            As[kq*4+0][r] = va.x; As[kq*4+1][r] = va.y; As[kq*4+2][r] = va.z; As[kq*4+3][r] = va.w;
            int j = j0 + r;
            const float* wr = (j < 192) ? (wmu + (size_t)j * 64) : (wsd + (size_t)(j - 192) * 64);
            float4 vw = *(const float4*)(wr + k0 + kq * 4);
            Ws[kq*4+0][r] = vw.x; Ws[kq*4+1][r] = vw.y; Ws[kq*4+2][r] = vw.z; Ws[kq*4+3][r] = vw.w;
        }
        __syncthreads();
#pragma unroll
        for (int kk = 0; kk < 16; kk++) {
            float4 a0 = *(const float4*)&As[kk][ty * 8];
            float4 a1 = *(const float4*)&As[kk][ty * 8 + 4];
            float4 b0 = *(const float4*)&Ws[kk][tx * 8];
            float4 b1 = *(const float4*)&Ws[kk][tx * 8 + 4];
            float a[8] = {a0.x,a0.y,a0.z,a0.w,a1.x,a1.y,a1.z,a1.w};
            float b[8] = {b0.x,b0.y,b0.z,b0.w,b1.x,b1.y,b1.z,b1.w};
#pragma unroll
            for (int i = 0; i < 8; i++)
#pragma unroll
                for (int j = 0; j < 8; j++) acc[i][j] += a[i] * b[j];
        }
        __syncthreads();
    }
#pragma unroll
    for (int i = 0; i < 8; i++) {
        int m = m0 + ty * 8 + i;
#pragma unroll
        for (int jj = 0; jj < 8; jj += 4) {
            int j = j0 + tx * 8 + jj;
            const float* bb = (j < 192) ? (bmu + j) : (bsd + j - 192);
            float4 v = make_float4(acc[i][jj]+bb[0], acc[i][jj+1]+bb[1], acc[i][jj+2]+bb[2], acc[i][jj+3]+bb[3]);
            *(float4*)(g_qkv_inter + (size_t)m * 384 + j) = v;
        }
    }
}

// ---- Kernel G: inter attention, key-split (8 lanes/query), padded smem rows ----
#define KV_STRIDE 20
__global__ void __launch_bounds__(256) k_inter_attn()
{
    __shared__ float ks[256 * KV_STRIDE];
    __shared__ float vs[256 * KV_STRIDE];
    const int bi = blockIdx.x;
    const int which = bi >> 7;
    const int h = (bi >> 5) & 3;
    const int qb = bi & 31;
    const int tid = threadIdx.x;
    const int ql = tid >> 3;
    const int lg = tid & 7;
    const int q = qb * 32 + ql;

    float4 qv[4];
    const float4* qp = (const float4*)(g_qkv_inter + (size_t)q * 384 + which * 192 + h * 16);
#pragma unroll
    for (int u = 0; u < 4; u++) {
        qv[u] = qp[u];
        qv[u].x *= 0.25f; qv[u].y *= 0.25f; qv[u].z *= 0.25f; qv[u].w *= 0.25f;
    }
    float sum = 0.f;
    float4 o[4];
#pragma unroll
    for (int u = 0; u < 4; u++) o[u] = make_float4(0.f, 0.f, 0.f, 0.f);

    for (int j0 = 0; j0 < 1024; j0 += 256) {
        __syncthreads();
#pragma unroll
        for (int l = 0; l < 8; l++) {
            int idx = tid + l * 256;
            int kv = idx >> 10, r = (idx >> 2) & 255, dq = idx & 3;
            float4 v = *(const float4*)(g_qkv_inter + (size_t)(j0 + r) * 384 + which * 192 + 64 + kv * 64 + h * 16 + dq * 4);
            *(float4*)((kv ? vs : ks) + r * KV_STRIDE + dq * 4) = v;
        }
        __syncthreads();
        for (int j = lg; j < 256; j += 8) {
            const float4* kr = (const float4*)(ks + j * KV_STRIDE);
            float s = 0.f;
#pragma unroll
            for (int u = 0; u < 4; u++) {
                float4 k = kr[u];
                s += qv[u].x * k.x + qv[u].y * k.y + qv[u].z * k.z + qv[u].w * k.w;
            }
            float p = __expf(s);
            sum += p;
            const float4* vr = (const float4*)(vs + j * KV_STRIDE);
#pragma unroll
            for (int u = 0; u < 4; u++) {
                float4 v = vr[u];
                o[u].x += p * v.x; o[u].y += p * v.y;
                o[u].z += p * v.z; o[u].w += p * v.w;
            }
        }
    }
#pragma unroll
    for (int off = 4; off >= 1; off >>= 1) {
        sum += __shfl_xor_sync(0xffffffffu, sum, off);
#pragma unroll
        for (int u = 0; u < 4; u++) {
            o[u].x += __shfl_xor_sync(0xffffffffu, o[u].x, off);
            o[u].y += __shfl_xor_sync(0xffffffffu, o[u].y, off);
            o[u].z += __shfl_xor_sync(0xffffffffu, o[u].z, off);
            o[u].w += __shfl_xor_sync(0xffffffffu, o[u].w, off);
        }
    }
    if (lg == 0) {
        float inv = 1.f / sum;
        float4* op = (float4*)(g_att_inter + (size_t)q * 128 + which * 64 + h * 16);
#pragma unroll
        for (int u = 0; u < 4; u++)
            op[u] = make_float4(o[u].x * inv, o[u].y * inv, o[u].z * inv, o[u].w * inv);
    }
}

// ---- Kernel H: inter out-proj + softplus + sample + broadcast ----
__global__ void __launch_bounds__(256) k_inter_out(
    const float* __restrict__ wmu, const float* __restrict__ bmu,
    const float* __restrict__ wsd, const float* __restrict__ bsd,
    const int* __restrict__ sets, const float* __restrict__ eps,
    float* __restrict__ out)
{
    __shared__ float a[128];
    __shared__ float mu[64], sd[64], sa[64];
    const int g = blockIdx.x, tid = threadIdx.x;
    if (tid < 128) a[tid] = g_att_inter[(size_t)g * 128 + tid];
    __syncthreads();
    if (tid < 64) {
        float acc = bmu[tid];
        const float* w = wmu + (size_t)tid * 64;
#pragma unroll 8
        for (int d = 0; d < 64; d++) acc += a[d] * w[d];
        mu[tid] = acc;
    } else if (tid < 128) {
        int j = tid - 64;
        float acc = bsd[j];
        const float* w = wsd + (size_t)j * 64;
#pragma unroll 8
        for (int d = 0; d < 64; d++) acc += a[64 + d] * w[d];
        float z = acc - 5.f;
        sd[j] = (z > 20.f) ? z : log1pf(__expf(z));
    }
    __syncthreads();
    if (tid < 64) sa[tid] = mu[tid] + sd[tid] * eps[(size_t)g * 64 + tid];
    __syncthreads();
    const size_t MU0 = (size_t)N_AG * 640, SD0 = MU0 + (size_t)N_AG * 128;
    for (int idx = tid; idx < 64 * 192; idx += 256) {
        int i = idx / 192, c = idx % 192;
        int agent = sets[g * 64 + i];
        if (c < 64)       out[(size_t)agent * 640 + 512 + c] = sa[c];
        else if (c < 128) out[MU0 + (size_t)agent * 128 + 64 + (c - 64)] = mu[c - 64];
        else              out[SD0 + (size_t)agent * 128 + 64 + (c - 128)] = sd[c - 128];
    }
}

extern "C" void kernel_launch(void* const* d_in, const int* in_sizes, int n_in,
                              void* d_out, int out_size)
{
    (void)in_sizes; (void)n_in; (void)out_size;
    const float* obs   = (const float*)d_in[0];
    const int*   sets  = (const int*)d_in[1];
    const float* eps_a = (const float*)d_in[2];
    const float* eps_e = (const float*)d_in[3];
    const float* lw    = (const float*)d_in[4];
    const float* lb    = (const float*)d_in[5];
    const float* iew   = (const float*)d_in[6];
    const float* ieb   = (const float*)d_in[7];
    const float* aew   = (const float*)d_in[8];
    const float* aeb   = (const float*)d_in[9];
    const float* amu_iw = (const float*)d_in[10];
    const float* amu_ib = (const float*)d_in[11];
    const float* amu_ow = (const float*)d_in[12];
    const float* amu_ob = (const float*)d_in[13];
    const float* asd_iw = (const float*)d_in[14];
    const float* asd_ib = (const float*)d_in[15];
    const float* asd_ow = (const float*)d_in[16];
    const float* asd_ob = (const float*)d_in[17];
    const float* emu_iw = (const float*)d_in[18];
    const float* emu_ib = (const float*)d_in[19];
    const float* emu_ow = (const float*)d_in[20];
    const float* emu_ob = (const float*)d_in[21];
    const float* esd_iw = (const float*)d_in[22];
    const float* esd_ib = (const float*)d_in[23];
    const float* esd_ow = (const float*)d_in[24];
    const float* esd_ob = (const float*)d_in[25];
    const float* aw    = (const float*)d_in[26];
    const float* ab    = (const float*)d_in[27];
    float* out = (float*)d_out;

    const int smem_fused = SMEM_FUSED_FLOATS * 4;
    const int smem_emb = EMB_STAGE * EMB_NSTAGE * 4;
    cudaFuncSetAttribute(k_intra_fused, cudaFuncAttributeMaxDynamicSharedMemorySize, smem_fused);
    cudaFuncSetAttribute(k_emb_tc, cudaFuncAttributeMaxDynamicSharedMemorySize, smem_emb);

    k_emb_tc<<<dim3(512, 5), 256, smem_emb>>>(obs, lw, lb, iew, ieb, aew, aeb, out);
    k_intra_fused<<<1024, 512, smem_fused>>>(sets,
        amu_iw, amu_ib, asd_iw, asd_ib,
        amu_ow, amu_ob, asd_ow, asd_ob,
        aw, ab, eps_a, out);
    k_qkv_inter_k<<<dim3(8, 3), 256>>>(emu_iw, emu_ib, esd_iw, esd_ib);
    k_inter_attn<<<256, 256>>>();
    k_inter_out<<<1024, 256>>>(emu_ow, emu_ob, esd_ow, esd_ob, sets, eps_e, out);
}

// round 17
// speedup vs baseline: 1.1959x; 1.1959x over previous
#include <cuda_runtime.h>
#include <math.h>
#include <stdint.h>

#define N_AG 65536
#define G_NUM 1024

static __device__ float g_inter_emb[(size_t)N_AG * 64];
static __device__ float g_intra_emb[(size_t)N_AG * 64];
static __device__ float g_pooled[G_NUM * 64];
static __device__ float g_qkv_inter[G_NUM * 384];
static __device__ float g_att_inter[G_NUM * 128];

__device__ __forceinline__ uint32_t f2tf32(float x) {
    uint32_t u;
    asm("cvt.rna.tf32.f32 %0, %1;" : "=r"(u) : "f"(x));
    return u;
}

__device__ __forceinline__ void mma_tf32(float* c, const uint32_t* a, const uint32_t* b) {
    asm volatile("mma.sync.aligned.m16n8k8.row.col.f32.tf32.tf32.f32 "
        "{%0,%1,%2,%3}, {%4,%5,%6,%7}, {%8,%9}, {%0,%1,%2,%3};"
        : "+f"(c[0]), "+f"(c[1]), "+f"(c[2]), "+f"(c[3])
        : "r"(a[0]), "r"(a[1]), "r"(a[2]), "r"(a[3]), "r"(b[0]), "r"(b[1]));
}

__device__ __forceinline__ void cp_async16(uint32_t smem_addr, const void* gptr) {
    asm volatile("cp.async.ca.shared.global [%0], [%1], 16;" :: "r"(smem_addr), "l"(gptr));
}
__device__ __forceinline__ void cp_commit() {
    asm volatile("cp.async.commit_group;");
}
template <int N>
__device__ __forceinline__ void cp_wait() {
    asm volatile("cp.async.wait_group %0;" :: "n"(N));
}

__device__ __forceinline__ float ftanh(float x) {
    return 1.f - __fdividef(2.f, __expf(2.f * x) + 1.f);
}

// ====== Kernel A: embedding GEMM (TF32 MMA, cp.async double-buffered — R15 structure) ======
#define EMB_STAGE 9216
__global__ void __launch_bounds__(256) k_emb_tc(const float* __restrict__ obs,
    const float* __restrict__ lw, const float* __restrict__ lb,
    const float* __restrict__ iew, const float* __restrict__ ieb,
    const float* __restrict__ aew, const float* __restrict__ aeb,
    float* __restrict__ out)
{
    extern __shared__ uint32_t dynsm[];
    const int tid = threadIdx.x;
    const int lane = tid & 31, warp = tid >> 5;
    const int wm = warp >> 2, wn = warp & 3;
    const int gid = lane >> 2, tg = lane & 3;
    const int m0 = blockIdx.x * 128, j0 = blockIdx.y * 128;

    const float* agp[4];
    const float* wgp[4];
    uint32_t sa_off[4], sw_off[4];
#pragma unroll
    for (int l = 0; l < 4; l++) {
        int slot = tid + l * 256;
        int r = slot >> 3, kq = slot & 7;
        agp[l] = obs + (size_t)(m0 + r) * 256 + kq * 4;
        int j = j0 + r;
        const float* wr = (j < 512) ? (lw + (size_t)j * 256)
                        : (j < 576) ? (iew + (size_t)(j - 512) * 256)
                        : (aew + (size_t)(j - 576) * 256);
        wgp[l] = wr + kq * 4;
        uint32_t base = (uint32_t)__cvta_generic_to_shared(dynsm);
        sa_off[l] = base + (r * 36 + kq * 4) * 4;
        sw_off[l] = base + (4608 + r * 36 + kq * 4) * 4;
    }

    float acc[4][4][4];
#pragma unroll
    for (int i = 0; i < 4; i++)
#pragma unroll
        for (int j = 0; j < 4; j++)
#pragma unroll
            for (int u = 0; u < 4; u++) acc[i][j][u] = 0.f;

#pragma unroll
    for (int l = 0; l < 4; l++) {
        cp_async16(sa_off[l], agp[l]);
        cp_async16(sw_off[l], wgp[l]);
    }
    cp_commit();

    for (int kc = 0; kc < 8; kc++) {
        if (kc + 1 < 8) {
            uint32_t soff = ((kc + 1) & 1) * (EMB_STAGE * 4);
#pragma unroll
            for (int l = 0; l < 4; l++) {
                cp_async16(sa_off[l] + soff, agp[l] + (kc + 1) * 32);
                cp_async16(sw_off[l] + soff, wgp[l] + (kc + 1) * 32);
            }
            cp_commit();
            cp_wait<1>();
        } else {
            cp_wait<0>();
        }
        __syncthreads();
        const uint32_t* As = dynsm + (kc & 1) * EMB_STAGE;
        const uint32_t* Ws = As + 4608;
#pragma unroll
        for (int k8 = 0; k8 < 4; k8++) {
            int kb = k8 * 8;
            uint32_t a[4][4], b[4][2];
#pragma unroll
            for (int mt = 0; mt < 4; mt++) {
                int row = wm * 64 + mt * 16;
                a[mt][0] = As[(row + gid) * 36 + kb + tg];
                a[mt][1] = As[(row + gid + 8) * 36 + kb + tg];
                a[mt][2] = As[(row + gid) * 36 + kb + tg + 4];
                a[mt][3] = As[(row + gid + 8) * 36 + kb + tg + 4];
            }
#pragma unroll
            for (int nt = 0; nt < 4; nt++) {
                int col = wn * 32 + nt * 8;
                b[nt][0] = Ws[(col + gid) * 36 + kb + tg];
                b[nt][1] = Ws[(col + gid) * 36 + kb + tg + 4];
            }
#pragma unroll
            for (int mt = 0; mt < 4; mt++)
#pragma unroll
                for (int nt = 0; nt < 4; nt++)
                    mma_tf32(acc[mt][nt], a[mt], b[nt]);
        }
        __syncthreads();
    }

#pragma unroll
    for (int mt = 0; mt < 4; mt++) {
#pragma unroll
        for (int nt = 0; nt < 4; nt++) {
            int col = j0 + wn * 32 + nt * 8 + 2 * tg;
#pragma unroll
            for (int half = 0; half < 2; half++) {
                int row = m0 + wm * 64 + mt * 16 + gid + half * 8;
                float v0 = acc[mt][nt][half * 2 + 0];
                float v1 = acc[mt][nt][half * 2 + 1];
                float2 r2;
                if (col < 512) {
                    r2.x = ftanh(v0 + lb[col]); r2.y = ftanh(v1 + lb[col + 1]);
                    *(float2*)(out + (size_t)row * 640 + col) = r2;
                } else if (col < 576) {
                    int c = col - 512;
                    r2.x = ftanh(v0 + ieb[c]); r2.y = ftanh(v1 + ieb[c + 1]);
                    *(float2*)(g_inter_emb + (size_t)row * 64 + c) = r2;
                } else {
                    int c = col - 576;
                    r2.x = ftanh(v0 + aeb[c]); r2.y = ftanh(v1 + aeb[c + 1]);
                    *(float2*)(g_intra_emb + (size_t)row * 64 + c) = r2;
                }
            }
        }
    }
}

// ======== Kernel B: fused intra path, 512 threads (R15, unchanged) ========
#define OFF_IE  4352
#define OFF_QKV 8704
#define OFF_ATT 33792
#define OFF_W   42496
#define OFF_LG  55552
#define OFF_PR  55616
#define SMEM_FUSED_FLOATS 55680

__global__ void __launch_bounds__(512) k_intra_fused(const int* __restrict__ sets,
    const float* __restrict__ wmu_in, const float* __restrict__ bmu_in,
    const float* __restrict__ wsd_in, const float* __restrict__ bsd_in,
    const float* __restrict__ wmu_out, const float* __restrict__ bmu_out,
    const float* __restrict__ wsd_out, const float* __restrict__ bsd_out,
    const float* __restrict__ aw, const float* __restrict__ ab,
    const float* __restrict__ eps, float* __restrict__ out)
{
    extern __shared__ float sm[];
    float* s_emb = sm;
    float* s_ie  = sm + OFF_IE;
    float* s_qkv = sm + OFF_QKV;
    float* s_att = sm + OFF_ATT;
    float* s_w   = sm + OFF_W;
    float* s_lg  = sm + OFF_LG;
    float* s_pr  = sm + OFF_PR;

    const int g = blockIdx.x, tid = threadIdx.x;
    const int lane = tid & 31, warp = tid >> 5;
    const int gid = lane >> 2, tg = lane & 3;

#pragma unroll
    for (int l = 0; l < 2; l++) {
        int idx = tid + l * 512;
        int r = idx >> 4, c4 = (idx & 15) * 4;
        int agent = sets[g * 64 + r];
        *(float4*)(s_emb + r * 68 + c4) = *(const float4*)(g_intra_emb + (size_t)agent * 64 + c4);
        *(float4*)(s_ie + r * 68 + c4)  = *(const float4*)(g_inter_emb + (size_t)agent * 64 + c4);
    }
    __syncthreads();

    if (tid < 64) {
        float a = ab[0];
#pragma unroll 8
        for (int d = 0; d < 64; d++) a += s_ie[tid * 68 + d] * aw[d];
        s_lg[tid] = a;
    }
#pragma unroll
    for (int l = 0; l < 6; l++) {
        int idx = tid + l * 512;
        int r = idx >> 4, c4 = (idx & 15) * 4;
        *(float4*)(s_w + r * 68 + c4) = *(const float4*)(wmu_in + (size_t)r * 64 + c4);
    }
    __syncthreads();

    if (tid < 64) {
        float mx = -1e30f;
        for (int s = 0; s < 64; s++) mx = fmaxf(mx, s_lg[s]);
        s_pr[tid] = __expf(s_lg[tid] - mx);
    }
    {
        const int wm = warp >> 2, wn = warp & 3;
        float acc[6][4];
#pragma unroll
        for (int nt = 0; nt < 6; nt++)
#pragma unroll
            for (int u = 0; u < 4; u++) acc[nt][u] = 0.f;
#pragma unroll
        for (int k8 = 0; k8 < 8; k8++) {
            int kb = k8 * 8;
            uint32_t a[4];
            a[0] = f2tf32(s_emb[(wm*16+gid)*68 + kb+tg]);
            a[1] = f2tf32(s_emb[(wm*16+gid+8)*68 + kb+tg]);
            a[2] = f2tf32(s_emb[(wm*16+gid)*68 + kb+tg+4]);
            a[3] = f2tf32(s_emb[(wm*16+gid+8)*68 + kb+tg+4]);
#pragma unroll
            for (int nt = 0; nt < 6; nt++) {
                int col = wn * 48 + nt * 8;
                uint32_t b[2];
                b[0] = f2tf32(s_w[(col+gid)*68 + kb+tg]);
                b[1] = f2tf32(s_w[(col+gid)*68 + kb+tg+4]);
                mma_tf32(acc[nt], a, b);
            }
        }
#pragma unroll
        for (int nt = 0; nt < 6; nt++) {
            int col = wn * 48 + nt * 8 + 2 * tg;
            float b0 = bmu_in[col], b1 = bmu_in[col + 1];
            *(float2*)(s_qkv + (wm*16+gid)*196 + col)   = make_float2(acc[nt][0]+b0, acc[nt][1]+b1);
            *(float2*)(s_qkv + (wm*16+gid+8)*196 + col) = make_float2(acc[nt][2]+b0, acc[nt][3]+b1);
        }
    }
    __syncthreads();

    if (tid < 64) {
        float sum = 0.f, acc = 0.f;
        for (int s = 0; s < 64; s++) sum += s_pr[s];
        for (int s = 0; s < 64; s++) acc += s_pr[s] * s_ie[s * 68 + tid];
        g_pooled[g * 64 + tid] = acc / sum;
    }
#pragma unroll
    for (int l = 0; l < 6; l++) {
        int idx = tid + l * 512;
        int r = idx >> 4, c4 = (idx & 15) * 4;
        *(float4*)(s_w + r * 68 + c4) = *(const float4*)(wsd_in + (size_t)r * 64 + c4);
    }
    __syncthreads();

    {
        const int wm = warp >> 2, wn = warp & 3;
        float acc[6][4];
#pragma unroll
        for (int nt = 0; nt < 6; nt++)
#pragma unroll
            for (int u = 0; u < 4; u++) acc[nt][u] = 0.f;
#pragma unroll
        for (int k8 = 0; k8 < 8; k8++) {
            int kb = k8 * 8;
            uint32_t a[4];
            a[0] = f2tf32(s_emb[(wm*16+gid)*68 + kb+tg]);
            a[1] = f2tf32(s_emb[(wm*16+gid+8)*68 + kb+tg]);
            a[2] = f2tf32(s_emb[(wm*16+gid)*68 + kb+tg+4]);
            a[3] = f2tf32(s_emb[(wm*16+gid+8)*68 + kb+tg+4]);
#pragma unroll
            for (int nt = 0; nt < 6; nt++) {
                int col = wn * 48 + nt * 8;
                uint32_t b[2];
                b[0] = f2tf32(s_w[(col+gid)*68 + kb+tg]);
                b[1] = f2tf32(s_w[(col+gid)*68 + kb+tg+4]);
                mma_tf32(acc[nt], a, b);
            }
        }
#pragma unroll
        for (int nt = 0; nt < 6; nt++) {
            int col = wn * 48 + nt * 8 + 2 * tg;
            float b0 = bsd_in[col], b1 = bsd_in[col + 1];
            *(float2*)(s_qkv + 12544 + (wm*16+gid)*196 + col)   = make_float2(acc[nt][0]+b0, acc[nt][1]+b1);
            *(float2*)(s_qkv + 12544 + (wm*16+gid+8)*196 + col) = make_float2(acc[nt][2]+b0, acc[nt][3]+b1);
        }
    }
    __syncthreads();

#pragma unroll
    for (int l = 0; l < 4; l++) {
        int idx = tid + l * 512;
        int w = idx >> 10, r = (idx >> 4) & 63, c4 = (idx & 15) * 4;
        *(float4*)(s_w + w * 4352 + r * 68 + c4) =
            *(const float4*)((w ? wsd_out : wmu_out) + (size_t)r * 64 + c4);
    }
    {
        const int w = tid >> 8, h = (tid >> 6) & 3, i = tid & 63;
        const float* base = s_qkv + w * 12544;
        float4 qv[4];
        const float4* qp = (const float4*)(base + i * 196 + h * 16);
#pragma unroll
        for (int u = 0; u < 4; u++) {
            qv[u] = qp[u];
            qv[u].x *= 0.25f; qv[u].y *= 0.25f; qv[u].z *= 0.25f; qv[u].w *= 0.25f;
        }
        float sum = 0.f;
        float4 o[4];
#pragma unroll
        for (int u = 0; u < 4; u++) o[u] = make_float4(0.f, 0.f, 0.f, 0.f);
        for (int j = 0; j < 64; j++) {
            const float4* kr = (const float4*)(base + j * 196 + 64 + h * 16);
            float s = 0.f;
#pragma unroll
            for (int u = 0; u < 4; u++) {
                float4 k = kr[u];
                s += qv[u].x * k.x + qv[u].y * k.y + qv[u].z * k.z + qv[u].w * k.w;
            }
            float p = __expf(s);
            sum += p;
            const float4* vr = (const float4*)(base + j * 196 + 128 + h * 16);
#pragma unroll
            for (int u = 0; u < 4; u++) {
                float4 v = vr[u];
                o[u].x += p * v.x; o[u].y += p * v.y; o[u].z += p * v.z; o[u].w += p * v.w;
            }
        }
        float inv = 1.f / sum;
        float4* op = (float4*)(s_att + w * 4352 + i * 68 + h * 16);
#pragma unroll
        for (int u = 0; u < 4; u++)
            op[u] = make_float4(o[u].x * inv, o[u].y * inv, o[u].z * inv, o[u].w * inv);
    }
    __syncthreads();

    {
        const int w = warp >> 3, ww = warp & 7;
        const int wm2 = ww >> 1, wn2 = ww & 1;
        const float* A = s_att + w * 4352;
        const float* B = s_w + w * 4352;
        const float* bb = w ? bsd_out : bmu_out;
        float am[4][4];
#pragma unroll
        for (int nt = 0; nt < 4; nt++)
#pragma unroll
            for (int u = 0; u < 4; u++) am[nt][u] = 0.f;
#pragma unroll
        for (int k8 = 0; k8 < 8; k8++) {
            int kb = k8 * 8;
            uint32_t a[4];
            a[0] = f2tf32(A[(wm2*16+gid)*68 + kb+tg]);
            a[1] = f2tf32(A[(wm2*16+gid+8)*68 + kb+tg]);
            a[2] = f2tf32(A[(wm2*16+gid)*68 + kb+tg+4]);
            a[3] = f2tf32(A[(wm2*16+gid+8)*68 + kb+tg+4]);
#pragma unroll
            for (int nt = 0; nt < 4; nt++) {
                int col = wn2 * 32 + nt * 8;
                uint32_t b[2];
                b[0] = f2tf32(B[(col+gid)*68 + kb+tg]);
                b[1] = f2tf32(B[(col+gid)*68 + kb+tg+4]);
                mma_tf32(am[nt], a, b);
            }
        }
#pragma unroll
        for (int nt = 0; nt < 4; nt++) {
            int col = wn2 * 32 + nt * 8 + 2 * tg;
            float b0 = bb[col], b1 = bb[col + 1];
#pragma unroll
            for (int half = 0; half < 2; half++) {
                int row = wm2 * 16 + gid + half * 8;
                *(float2*)(s_qkv + w * 4352 + row * 68 + col) =
                    make_float2(am[nt][half*2+0] + b0, am[nt][half*2+1] + b1);
            }
        }
    }
    __syncthreads();

    {
        const int i = tid >> 3, c0 = (tid & 7) * 8;
        const int agent = sets[g * 64 + i];
        const size_t MU0 = (size_t)N_AG * 640, SD0 = MU0 + (size_t)N_AG * 128;
        float mu[8], sd[8], sa[8];
#pragma unroll
        for (int jj = 0; jj < 8; jj++) {
            mu[jj] = s_qkv[i * 68 + c0 + jj];
            float z = s_qkv[4352 + i * 68 + c0 + jj] - 5.f;
            sd[jj] = (z > 20.f) ? z : log1pf(__expf(z));
        }
#pragma unroll
        for (int jj = 0; jj < 8; jj++)
            sa[jj] = mu[jj] + sd[jj] * eps[(size_t)agent * 64 + c0 + jj];
        float* oa = out + (size_t)agent * 640 + 576 + c0;
        float* om = out + MU0 + (size_t)agent * 128 + c0;
        float* os = out + SD0 + (size_t)agent * 128 + c0;
#pragma unroll
        for (int jj = 0; jj < 8; jj += 4) {
            *(float4*)(oa + jj) = make_float4(sa[jj], sa[jj+1], sa[jj+2], sa[jj+3]);
            *(float4*)(om + jj) = make_float4(mu[jj], mu[jj+1], mu[jj+2], mu[jj+3]);
            *(float4*)(os + jj) = make_float4(sd[jj], sd[jj+1], sd[jj+2], sd[jj+3]);
        }
    }
}

// ---- Kernel F: inter QKV GEMM (small, fp32) ----
__global__ void __launch_bounds__(256) k_qkv_inter_k(
    const float* __restrict__ wmu, const float* __restrict__ bmu,
    const float* __restrict__ wsd, const float* __restrict__ bsd)
{
    __shared__ float As[16][132];
    __shared__ float Ws[16][132];
    const int tid = threadIdx.x, tx = tid & 15, ty = tid >> 4;
    const int m0 = blockIdx.x * 128, j0 = blockIdx.y * 128;
    float acc[8][8];
#pragma unroll
    for (int i = 0; i < 8; i++)
#pragma unroll
        for (int j = 0; j < 8; j++) acc[i][j] = 0.f;
    for (int k0 = 0; k0 < 64; k0 += 16) {
#pragma unroll
        for (int l = 0; l < 2; l++) {
            int idx = tid + l * 256;
            int r = idx >> 2, kq = idx & 3;
            float4 va = *(const float4*)(g_pooled + (size_t)(m0 + r) * 64 + k0 + kq * 4);
            As[kq*4+0][r] = va.x; As[kq*4+1][r] = va.y; As[kq*4+2][r] = va.z; As[kq*4+3][r] = va.w;
            int j = j0 + r;
            const float* wr = (j < 192) ? (wmu + (size_t)j * 64) : (wsd + (size_t)(j - 192) * 64);
            float4 vw = *(const float4*)(wr + k0 + kq * 4);
            Ws[kq*4+0][r] = vw.x; Ws[kq*4+1][r] = vw.y; Ws[kq*4+2][r] = vw.z; Ws[kq*4+3][r] = vw.w;
        }
        __syncthreads();
#pragma unroll
        for (int kk = 0; kk < 16; kk++) {
            float4 a0 = *(const float4*)&As[kk][ty * 8];
            float4 a1 = *(const float4*)&As[kk][ty * 8 + 4];
            float4 b0 = *(const float4*)&Ws[kk][tx * 8];
            float4 b1 = *(const float4*)&Ws[kk][tx * 8 + 4];
            float a[8] = {a0.x,a0.y,a0.z,a0.w,a1.x,a1.y,a1.z,a1.w};
            float b[8] = {b0.x,b0.y,b0.z,b0.w,b1.x,b1.y,b1.z,b1.w};
#pragma unroll
            for (int i = 0; i < 8; i++)
#pragma unroll
                for (int j = 0; j < 8; j++) acc[i][j] += a[i] * b[j];
        }
        __syncthreads();
    }
#pragma unroll
    for (int i = 0; i < 8; i++) {
        int m = m0 + ty * 8 + i;
#pragma unroll
        for (int jj = 0; jj < 8; jj += 4) {
            int j = j0 + tx * 8 + jj;
            const float* bb = (j < 192) ? (bmu + j) : (bsd + j - 192);
            float4 v = make_float4(acc[i][jj]+bb[0], acc[i][jj+1]+bb[1], acc[i][jj+2]+bb[2], acc[i][jj+3]+bb[3]);
            *(float4*)(g_qkv_inter + (size_t)m * 384 + j) = v;
        }
    }
}

// ---- Kernel G: inter attention, key-split, 2 queries/thread (K/V LDS reuse) ----
#define KV_STRIDE 20
__global__ void __launch_bounds__(256) k_inter_attn()
{
    __shared__ float ks[256 * KV_STRIDE];
    __shared__ float vs[256 * KV_STRIDE];
    const int bi = blockIdx.x;
    const int which = bi >> 6;            // 0..1
    const int h = (bi >> 4) & 3;          // 0..3
    const int qb = bi & 15;               // 0..15 (64 queries per block)
    const int tid = threadIdx.x;
    const int ql = tid >> 3;              // 0..31
    const int lg = tid & 7;               // 0..7
    const int q0 = qb * 64 + ql;
    const int q1 = q0 + 32;

    float4 qv0[4], qv1[4];
    {
        const float4* qp0 = (const float4*)(g_qkv_inter + (size_t)q0 * 384 + which * 192 + h * 16);
        const float4* qp1 = (const float4*)(g_qkv_inter + (size_t)q1 * 384 + which * 192 + h * 16);
#pragma unroll
        for (int u = 0; u < 4; u++) {
            qv0[u] = qp0[u];
            qv0[u].x *= 0.25f; qv0[u].y *= 0.25f; qv0[u].z *= 0.25f; qv0[u].w *= 0.25f;
            qv1[u] = qp1[u];
            qv1[u].x *= 0.25f; qv1[u].y *= 0.25f; qv1[u].z *= 0.25f; qv1[u].w *= 0.25f;
        }
    }
    float sum0 = 0.f, sum1 = 0.f;
    float4 o0[4], o1[4];
#pragma unroll
    for (int u = 0; u < 4; u++) { o0[u] = make_float4(0.f,0.f,0.f,0.f); o1[u] = make_float4(0.f,0.f,0.f,0.f); }

    for (int j0i = 0; j0i < 1024; j0i += 256) {
        __syncthreads();
#pragma unroll
        for (int l = 0; l < 8; l++) {
            int idx = tid + l * 256;
            int kv = idx >> 10, r = (idx >> 2) & 255, dq = idx & 3;
            float4 v = *(const float4*)(g_qkv_inter + (size_t)(j0i + r) * 384 + which * 192 + 64 + kv * 64 + h * 16 + dq * 4);
            *(float4*)((kv ? vs : ks) + r * KV_STRIDE + dq * 4) = v;
        }
        __syncthreads();
        for (int j = lg; j < 256; j += 8) {
            const float4* kr = (const float4*)(ks + j * KV_STRIDE);
            float4 k0v = kr[0], k1v = kr[1], k2v = kr[2], k3v = kr[3];
            float s0 = qv0[0].x*k0v.x + qv0[0].y*k0v.y + qv0[0].z*k0v.z + qv0[0].w*k0v.w
                     + qv0[1].x*k1v.x + qv0[1].y*k1v.y + qv0[1].z*k1v.z + qv0[1].w*k1v.w
                     + qv0[2].x*k2v.x + qv0[2].y*k2v.y + qv0[2].z*k2v.z + qv0[2].w*k2v.w
                     + qv0[3].x*k3v.x + qv0[3].y*k3v.y + qv0[3].z*k3v.z + qv0[3].w*k3v.w;
            float s1 = qv1[0].x*k0v.x + qv1[0].y*k0v.y + qv1[0].z*k0v.z + qv1[0].w*k0v.w
                     + qv1[1].x*k1v.x + qv1[1].y*k1v.y + qv1[1].z*k1v.z + qv1[1].w*k1v.w
                     + qv1[2].x*k2v.x + qv1[2].y*k2v.y + qv1[2].z*k2v.z + qv1[2].w*k2v.w
                     + qv1[3].x*k3v.x + qv1[3].y*k3v.y + qv1[3].z*k3v.z + qv1[3].w*k3v.w;
            float p0 = __expf(s0), p1 = __expf(s1);
            sum0 += p0; sum1 += p1;
            const float4* vr = (const float4*)(vs + j * KV_STRIDE);
#pragma unroll
            for (int u = 0; u < 4; u++) {
                float4 v = vr[u];
                o0[u].x += p0 * v.x; o0[u].y += p0 * v.y; o0[u].z += p0 * v.z; o0[u].w += p0 * v.w;
                o1[u].x += p1 * v.x; o1[u].y += p1 * v.y; o1[u].z += p1 * v.z; o1[u].w += p1 * v.w;
            }
        }
    }
#pragma unroll
    for (int off = 4; off >= 1; off >>= 1) {
        sum0 += __shfl_xor_sync(0xffffffffu, sum0, off);
        sum1 += __shfl_xor_sync(0xffffffffu, sum1, off);
#pragma unroll
        for (int u = 0; u < 4; u++) {
            o0[u].x += __shfl_xor_sync(0xffffffffu, o0[u].x, off);
            o0[u].y += __shfl_xor_sync(0xffffffffu, o0[u].y, off);
            o0[u].z += __shfl_xor_sync(0xffffffffu, o0[u].z, off);
            o0[u].w += __shfl_xor_sync(0xffffffffu, o0[u].w, off);
            o1[u].x += __shfl_xor_sync(0xffffffffu, o1[u].x, off);
            o1[u].y += __shfl_xor_sync(0xffffffffu, o1[u].y, off);
            o1[u].z += __shfl_xor_sync(0xffffffffu, o1[u].z, off);
            o1[u].w += __shfl_xor_sync(0xffffffffu, o1[u].w, off);
        }
    }
    if (lg == 0) {
        float i0 = 1.f / sum0, i1 = 1.f / sum1;
        float4* op0 = (float4*)(g_att_inter + (size_t)q0 * 128 + which * 64 + h * 16);
        float4* op1 = (float4*)(g_att_inter + (size_t)q1 * 128 + which * 64 + h * 16);
#pragma unroll
        for (int u = 0; u < 4; u++) {
            op0[u] = make_float4(o0[u].x * i0, o0[u].y * i0, o0[u].z * i0, o0[u].w * i0);
            op1[u] = make_float4(o1[u].x * i1, o1[u].y * i1, o1[u].z * i1, o1[u].w * i1);
        }
    }
}

// ---- Kernel H: inter out-proj + softplus + sample + broadcast ----
__global__ void __launch_bounds__(256) k_inter_out(
    const float* __restrict__ wmu, const float* __restrict__ bmu,
    const float* __restrict__ wsd, const float* __restrict__ bsd,
    const int* __restrict__ sets, const float* __restrict__ eps,
    float* __restrict__ out)
{
    __shared__ float a[128];
    __shared__ float mu[64], sd[64], sa[64];
    const int g = blockIdx.x, tid = threadIdx.x;
    if (tid < 128) a[tid] = g_att_inter[(size_t)g * 128 + tid];
    __syncthreads();
    if (tid < 64) {
        float acc = bmu[tid];
        const float* w = wmu + (size_t)tid * 64;
#pragma unroll 8
        for (int d = 0; d < 64; d++) acc += a[d] * w[d];
        mu[tid] = acc;
    } else if (tid < 128) {
        int j = tid - 64;
        float acc = bsd[j];
        const float* w = wsd + (size_t)j * 64;
#pragma unroll 8
        for (int d = 0; d < 64; d++) acc += a[64 + d] * w[d];
        float z = acc - 5.f;
        sd[j] = (z > 20.f) ? z : log1pf(__expf(z));
    }
    __syncthreads();
    if (tid < 64) sa[tid] = mu[tid] + sd[tid] * eps[(size_t)g * 64 + tid];
    __syncthreads();
    const size_t MU0 = (size_t)N_AG * 640, SD0 = MU0 + (size_t)N_AG * 128;
    for (int idx = tid; idx < 64 * 192; idx += 256) {
        int i = idx / 192, c = idx % 192;
        int agent = sets[g * 64 + i];
        if (c < 64)       out[(size_t)agent * 640 + 512 + c] = sa[c];
        else if (c < 128) out[MU0 + (size_t)agent * 128 + 64 + (c - 64)] = mu[c - 64];
        else              out[SD0 + (size_t)agent * 128 + 64 + (c - 128)] = sd[c - 128];
    }
}

extern "C" void kernel_launch(void* const* d_in, const int* in_sizes, int n_in,
                              void* d_out, int out_size)
{
    (void)in_sizes; (void)n_in; (void)out_size;
    const float* obs   = (const float*)d_in[0];
    const int*   sets  = (const int*)d_in[1];
    const float* eps_a = (const float*)d_in[2];
    const float* eps_e = (const float*)d_in[3];
    const float* lw    = (const float*)d_in[4];
    const float* lb    = (const float*)d_in[5];
    const float* iew   = (const float*)d_in[6];
    const float* ieb   = (const float*)d_in[7];
    const float* aew   = (const float*)d_in[8];
    const float* aeb   = (const float*)d_in[9];
    const float* amu_iw = (const float*)d_in[10];
    const float* amu_ib = (const float*)d_in[11];
    const float* amu_ow = (const float*)d_in[12];
    const float* amu_ob = (const float*)d_in[13];
    const float* asd_iw = (const float*)d_in[14];
    const float* asd_ib = (const float*)d_in[15];
    const float* asd_ow = (const float*)d_in[16];
    const float* asd_ob = (const float*)d_in[17];
    const float* emu_iw = (const float*)d_in[18];
    const float* emu_ib = (const float*)d_in[19];
    const float* emu_ow = (const float*)d_in[20];
    const float* emu_ob = (const float*)d_in[21];
    const float* esd_iw = (const float*)d_in[22];
    const float* esd_ib = (const float*)d_in[23];
    const float* esd_ow = (const float*)d_in[24];
    const float* esd_ob = (const float*)d_in[25];
    const float* aw    = (const float*)d_in[26];
    const float* ab    = (const float*)d_in[27];
    float* out = (float*)d_out;

    const int smem_fused = SMEM_FUSED_FLOATS * 4;
    const int smem_emb = EMB_STAGE * 2 * 4;
    cudaFuncSetAttribute(k_intra_fused, cudaFuncAttributeMaxDynamicSharedMemorySize, smem_fused);
    cudaFuncSetAttribute(k_emb_tc, cudaFuncAttributeMaxDynamicSharedMemorySize, smem_emb);

    k_emb_tc<<<dim3(512, 5), 256, smem_emb>>>(obs, lw, lb, iew, ieb, aew, aeb, out);
    k_intra_fused<<<1024, 512, smem_fused>>>(sets,
        amu_iw, amu_ib, asd_iw, asd_ib,
        amu_ow, amu_ob, asd_ow, asd_ob,
        aw, ab, eps_a, out);
    k_qkv_inter_k<<<dim3(8, 3), 256>>>(emu_iw, emu_ib, esd_iw, esd_ib);
    k_inter_attn<<<128, 256>>>();
    k_inter_out<<<1024, 256>>>(emu_ow, emu_ob, esd_ow, esd_ob, sets, eps_e, out);
}